// round 3
// baseline (speedup 1.0000x reference)
#include <cuda_runtime.h>
#include <cstdint>
#include <math.h>

#define TT 2048
#define BB 32
#define DD 512
#define HH 512
#define GG 2048        // 4*H
#define NCTA 128       // persistent CTAs (one wave, <= 148 SMs)
#define RTHREADS 256

// ---------------- device scratch (static, no allocs) ----------------
__device__ __align__(16) float g_pre[(size_t)TT * GG * BB];   // [t][gate][b], 512 MB
__device__ __align__(16) float g_hbuf[2][HH * BB];            // ping-pong h, [k][b]
__device__ unsigned g_count;                                  // barrier counter (returns to 0)
__device__ volatile unsigned g_sense;                         // barrier sense (even flips/launch)

// ---------------- packed fp32x2 helpers ----------------
__device__ __forceinline__ unsigned long long pk2(float lo, float hi) {
    unsigned long long r;
    asm("mov.b64 %0, {%1, %2};" : "=l"(r) : "f"(lo), "f"(hi));
    return r;
}
__device__ __forceinline__ void upk2(unsigned long long v, float& lo, float& hi) {
    asm("mov.b64 {%0, %1}, %2;" : "=f"(lo), "=f"(hi) : "l"(v));
}
__device__ __forceinline__ void ffma2(unsigned long long& acc, unsigned long long a,
                                      unsigned long long b) {
    asm("fma.rn.f32x2 %0, %1, %2, %0;" : "+l"(acc) : "l"(a), "l"(b));
}

// =====================================================================
// Kernel A: pre[t][g][b] = sum_k x[t][b][k] * w_ih[g][k] + b_ih[g]
// M = T*B = 65536 (m = t*32+b), N = 2048, K = 512.  FFMA2 SGEMM.
// =====================================================================
#define BM 128
#define BN 64
#define BK 16

__global__ __launch_bounds__(256) void pre_gemm(const float* __restrict__ x,
                                                const float* __restrict__ w,
                                                const float* __restrict__ bias) {
    __shared__ __align__(16) float As[BK][BM];   // transposed: [k][m]
    __shared__ __align__(16) float Bs[BK][BN];   // transposed: [k][n]

    const int m0 = blockIdx.y * BM;
    const int n0 = blockIdx.x * BN;
    const int tid = threadIdx.x;
    const int tx = tid & 15;   // n direction, 4 cols each
    const int ty = tid >> 4;   // m direction, 8 rows each

    unsigned long long acc[4][4];   // [m-pair][n], pairs along m
#pragma unroll
    for (int i = 0; i < 4; i++)
#pragma unroll
        for (int j = 0; j < 4; j++) acc[i][j] = 0ull;

    for (int k0 = 0; k0 < DD; k0 += BK) {
        // load A tile (128x16) transposed: 512 float4, 2 per thread
#pragma unroll
        for (int l = 0; l < 2; l++) {
            int p = tid + l * 256;
            int row = p >> 2, kq = (p & 3) * 4;
            float4 v = *(const float4*)&x[(size_t)(m0 + row) * DD + k0 + kq];
            As[kq + 0][row] = v.x; As[kq + 1][row] = v.y;
            As[kq + 2][row] = v.z; As[kq + 3][row] = v.w;
        }
        {   // load B tile (64x16) transposed: 256 float4, 1 per thread
            int row = tid >> 2, kq = (tid & 3) * 4;
            float4 v = *(const float4*)&w[(size_t)(n0 + row) * DD + k0 + kq];
            Bs[kq + 0][row] = v.x; Bs[kq + 1][row] = v.y;
            Bs[kq + 2][row] = v.z; Bs[kq + 3][row] = v.w;
        }
        __syncthreads();

#pragma unroll
        for (int k = 0; k < BK; k++) {
            float4 a01 = *(const float4*)&As[k][ty * 8];
            float4 a23 = *(const float4*)&As[k][ty * 8 + 4];
            float4 bf  = *(const float4*)&Bs[k][tx * 4];
            unsigned long long A[4] = { pk2(a01.x, a01.y), pk2(a01.z, a01.w),
                                        pk2(a23.x, a23.y), pk2(a23.z, a23.w) };
            unsigned long long Bv[4] = { pk2(bf.x, bf.x), pk2(bf.y, bf.y),
                                         pk2(bf.z, bf.z), pk2(bf.w, bf.w) };
#pragma unroll
            for (int i = 0; i < 4; i++)
#pragma unroll
                for (int j = 0; j < 4; j++) ffma2(acc[i][j], A[i], Bv[j]);
        }
        __syncthreads();
    }

    // epilogue: write g_pre[t][n][b] (+bias), m = t*32 + b
#pragma unroll
    for (int j = 0; j < 4; j++) {
        int n = n0 + tx * 4 + j;
        float bsv = bias[n];
#pragma unroll
        for (int i = 0; i < 4; i++) {
            float lo, hi;
            upk2(acc[i][j], lo, hi);
            int m_lo = m0 + ty * 8 + i * 2;
            int t0 = m_lo >> 5, b_lo = m_lo & 31;
            g_pre[(size_t)t0 * GG * BB + (size_t)n * BB + b_lo] = lo + bsv;
            int m_hi = m_lo + 1;
            int t1 = m_hi >> 5, b_hi = m_hi & 31;
            g_pre[(size_t)t1 * GG * BB + (size_t)n * BB + b_hi] = hi + bsv;
        }
    }
}

// =====================================================================
// Kernel B: persistent recurrent kernel.
// 128 CTAs; CTA c owns cells j in [4c, 4c+4) => 16 gate rows
// (rows q*512 + j0 + cell for q = i,f,g,o). w_hh slice packed into SMEM
// once; h staged (duplicated {h,h}) per step; one grid barrier per step.
// =====================================================================
struct __align__(16) SmemR {
    float2 wp[8][HH];       // [warp][k]: {w[row(2w)][k], w[row(2w+1)][k]}   32 KB
    float2 h2[HH][BB];      // duplicated h: [k][b] = {h,h}                 128 KB
    float  gates[16][BB];   // [rr][b], rr = q*4 + cell                       2 KB
    float  cst[4 * BB];     // cell state [cell][b]                         0.5 KB
};

__global__ __launch_bounds__(RTHREADS, 1) void lstm_recur(
    const float* __restrict__ h0, const float* __restrict__ c0,
    const float* __restrict__ w_hh, const float* __restrict__ b_hh,
    float* __restrict__ out, int write_state) {
    extern __shared__ char smem_raw[];
    SmemR* s = (SmemR*)smem_raw;

    const int tid = threadIdx.x;
    const int w = tid >> 5, lane = tid & 31;
    const int j0 = blockIdx.x * 4;   // cell base

    // this warp's two gate rows: rr -> (q = rr>>2, cell = rr&3)
    const int rr0 = 2 * w, rr1 = 2 * w + 1;
    const int r0 = (rr0 >> 2) * HH + j0 + (rr0 & 3);
    const int r1 = (rr1 >> 2) * HH + j0 + (rr1 & 3);
    const float bh0 = b_hh[r0], bh1 = b_hh[r1];

    // load packed w_hh slice into SMEM (once for all 2048 steps)
    for (int idx = tid; idx < 8 * HH; idx += RTHREADS) {
        int wi = idx >> 9, k = idx & 511;
        int a0 = 2 * wi, a1 = 2 * wi + 1;
        int ra = (a0 >> 2) * HH + j0 + (a0 & 3);
        int rb = (a1 >> 2) * HH + j0 + (a1 & 3);
        s->wp[wi][k] = make_float2(w_hh[(size_t)ra * HH + k], w_hh[(size_t)rb * HH + k]);
    }
    if (tid < 128) {
        int cell = tid >> 5, b = tid & 31;
        s->cst[cell * BB + b] = c0[(size_t)b * HH + j0 + cell];
    }
    __syncthreads();

    float h_keep = 0.f, c_keep = 0.f;

    for (int t = 0; t < TT; t++) {
        // ---- stage h into SMEM (duplicated), L2-coherent path ----
        if (t == 0) {
            for (int idx = tid; idx < HH * BB; idx += RTHREADS) {
                int k = idx >> 5, b = idx & 31;
                float hv = h0[(size_t)b * HH + k];
                s->h2[k][b] = make_float2(hv, hv);
            }
        } else {
            const float4* hb = (const float4*)g_hbuf[t & 1];
            for (int idx = tid; idx < (HH * BB) / 4; idx += RTHREADS) {
                float4 v = __ldcg(hb + idx);
                int base = idx * 4;           // = k*32 + b
                int k = base >> 5, b = base & 31;
                s->h2[k][b + 0] = make_float2(v.x, v.x);
                s->h2[k][b + 1] = make_float2(v.y, v.y);
                s->h2[k][b + 2] = make_float2(v.z, v.z);
                s->h2[k][b + 3] = make_float2(v.w, v.w);
            }
        }
        // prefetch precomputed x-contribution for this warp's rows
        float p0 = __ldcg(&g_pre[(size_t)t * GG * BB + (size_t)r0 * BB + lane]);
        float p1 = __ldcg(&g_pre[(size_t)t * GG * BB + (size_t)r1 * BB + lane]);
        __syncthreads();

        // ---- gate GEMM: 2 rows x 32 batches per warp, K=512, FFMA2 ----
        unsigned long long accA = pk2(p0 + bh0, p1 + bh1);
        unsigned long long accB = 0ull;
        const float4* wv4 = (const float4*)s->wp[w];
#pragma unroll 8
        for (int kk = 0; kk < HH / 2; kk++) {
            float4 wv = wv4[kk];                   // wp[w][2kk], wp[w][2kk+1]
            int k = kk * 2;
            unsigned long long hp0 = *(const unsigned long long*)&s->h2[k][lane];
            unsigned long long hp1 = *(const unsigned long long*)&s->h2[k + 1][lane];
            ffma2(accA, hp0, pk2(wv.x, wv.y));
            ffma2(accB, hp1, pk2(wv.z, wv.w));
        }
        float aLo, aHi, bLo, bHi;
        upk2(accA, aLo, aHi);
        upk2(accB, bLo, bHi);
        s->gates[rr0][lane] = aLo + bLo;
        s->gates[rr1][lane] = aHi + bHi;
        __syncthreads();

        // ---- cell update: 4 cells x 32 batches = 128 threads ----
        if (tid < 128) {
            int cell = tid >> 5, b = tid & 31;
            float gi = s->gates[0 + cell][b];
            float gf = s->gates[4 + cell][b];
            float gg = s->gates[8 + cell][b];
            float go = s->gates[12 + cell][b];
            float i_ = 1.f / (1.f + expf(-gi));
            float f_ = 1.f / (1.f + expf(-gf));
            float g_ = tanhf(gg);
            float o_ = 1.f / (1.f + expf(-go));
            float c_ = f_ * s->cst[cell * BB + b] + i_ * g_;
            float h_ = o_ * tanhf(c_);
            s->cst[cell * BB + b] = c_;
            int j = j0 + cell;
            __stcg(&g_hbuf[(t + 1) & 1][j * BB + b], h_);            // next step's h
            out[(size_t)t * BB * HH + (size_t)b * HH + j] = h_;       // outputs[t]
            h_keep = h_;
            c_keep = c_;
        }
        __threadfence();

        // ---- grid barrier (sense-reversing; 2048 flips/launch => replay-safe) ----
        {
            unsigned sense = (t & 1u) ^ 1u;
            __syncthreads();
            if (tid == 0) {
                unsigned arrived = atomicAdd(&g_count, 1u);
                if (arrived == NCTA - 1) {
                    atomicExch(&g_count, 0u);
                    __threadfence();
                    g_sense = sense;
                } else {
                    while (g_sense != sense) { __nanosleep(20); }
                    __threadfence();
                }
            }
            __syncthreads();
        }
    }

    // final (h, c) state after outputs, if the output buffer carries them
    if (write_state && tid < 128) {
        int cell = tid >> 5, b = tid & 31;
        int j = j0 + cell;
        out[(size_t)TT * BB * HH + (size_t)b * HH + j] = h_keep;
        out[(size_t)TT * BB * HH + (size_t)BB * HH + (size_t)b * HH + j] = c_keep;
    }
}

// =====================================================================
// launch
// =====================================================================
extern "C" void kernel_launch(void* const* d_in, const int* in_sizes, int n_in,
                              void* d_out, int out_size) {
    const float* x    = (const float*)d_in[0];
    const float* h0   = (const float*)d_in[1];
    const float* c0   = (const float*)d_in[2];
    const float* w_ih = (const float*)d_in[3];
    const float* w_hh = (const float*)d_in[4];
    const float* b_ih = (const float*)d_in[5];
    const float* b_hh = (const float*)d_in[6];
    float* out = (float*)d_out;

    dim3 gridA(GG / BN, (TT * BB) / BM);   // 32 x 512
    pre_gemm<<<gridA, 256>>>(x, w_ih, b_ih);

    int smem = (int)sizeof(SmemR);
    cudaFuncSetAttribute(lstm_recur, cudaFuncAttributeMaxDynamicSharedMemorySize, smem);
    int write_state = (out_size >= TT * BB * HH + 2 * BB * HH) ? 1 : 0;
    lstm_recur<<<NCTA, RTHREADS, smem>>>(h0, c0, w_hh, b_hh, out, write_state);
}

// round 5
// speedup vs baseline: 1.4721x; 1.4721x over previous
#include <cuda_runtime.h>
#include <cstdint>
#include <math.h>

#define TT 2048
#define BB 32
#define DD 512
#define HH 512
#define GG 2048        // 4*H
#define NCTA 128       // persistent CTAs (one wave)
#define RTHREADS 256
#define HPAD 518       // hT row stride: even (8B loads) and 259 ≡ odd mod 32 -> conflict-free LDS.64

// ---------------- device scratch (static, no allocs) ----------------
__device__ __align__(16) float g_pre[(size_t)TT * GG * BB];   // [t][gate_row][b]
__device__ __align__(16) float g_hbuf[2][BB * HH];            // ping-pong h, [b][k]
__device__ unsigned g_count;
__device__ volatile unsigned g_sense;

// ---------------- packed fp32x2 helpers ----------------
__device__ __forceinline__ unsigned long long pk2(float lo, float hi) {
    unsigned long long r;
    asm("mov.b64 %0, {%1, %2};" : "=l"(r) : "f"(lo), "f"(hi));
    return r;
}
__device__ __forceinline__ void upk2(unsigned long long v, float& lo, float& hi) {
    asm("mov.b64 {%0, %1}, %2;" : "=f"(lo), "=f"(hi) : "l"(v));
}
__device__ __forceinline__ void ffma2(unsigned long long& acc, unsigned long long a,
                                      unsigned long long b) {
    asm("fma.rn.f32x2 %0, %1, %2, %0;" : "+l"(acc) : "l"(a), "l"(b));
}
__device__ __forceinline__ float sigmoid_f(float x) {
    return __fdividef(1.f, 1.f + __expf(-x));
}
__device__ __forceinline__ float tanh_f(float x) {
    return 2.f * __fdividef(1.f, 1.f + __expf(-2.f * x)) - 1.f;
}

// =====================================================================
// Kernel A: pre[t][g][b] = sum_k x[t][b][k] * w_ih[g][k] + b_ih[g]
// M = T*B = 65536 (m = t*32+b), N = 2048, K = 512.  FFMA2 SGEMM.
// =====================================================================
#define BM 128
#define BN 64
#define BK 16

__global__ __launch_bounds__(256) void pre_gemm(const float* __restrict__ x,
                                                const float* __restrict__ w,
                                                const float* __restrict__ bias) {
    __shared__ __align__(16) float As[BK][BM];
    __shared__ __align__(16) float Bs[BK][BN];

    const int m0 = blockIdx.y * BM;
    const int n0 = blockIdx.x * BN;
    const int tid = threadIdx.x;
    const int tx = tid & 15;
    const int ty = tid >> 4;

    unsigned long long acc[4][4];
#pragma unroll
    for (int i = 0; i < 4; i++)
#pragma unroll
        for (int j = 0; j < 4; j++) acc[i][j] = 0ull;

    for (int k0 = 0; k0 < DD; k0 += BK) {
#pragma unroll
        for (int l = 0; l < 2; l++) {
            int p = tid + l * 256;
            int row = p >> 2, kq = (p & 3) * 4;
            float4 v = *(const float4*)&x[(size_t)(m0 + row) * DD + k0 + kq];
            As[kq + 0][row] = v.x; As[kq + 1][row] = v.y;
            As[kq + 2][row] = v.z; As[kq + 3][row] = v.w;
        }
        {
            int row = tid >> 2, kq = (tid & 3) * 4;
            float4 v = *(const float4*)&w[(size_t)(n0 + row) * DD + k0 + kq];
            Bs[kq + 0][row] = v.x; Bs[kq + 1][row] = v.y;
            Bs[kq + 2][row] = v.z; Bs[kq + 3][row] = v.w;
        }
        __syncthreads();

#pragma unroll
        for (int k = 0; k < BK; k++) {
            float4 a01 = *(const float4*)&As[k][ty * 8];
            float4 a23 = *(const float4*)&As[k][ty * 8 + 4];
            float4 bf  = *(const float4*)&Bs[k][tx * 4];
            unsigned long long A[4] = { pk2(a01.x, a01.y), pk2(a01.z, a01.w),
                                        pk2(a23.x, a23.y), pk2(a23.z, a23.w) };
            unsigned long long Bv[4] = { pk2(bf.x, bf.x), pk2(bf.y, bf.y),
                                         pk2(bf.z, bf.z), pk2(bf.w, bf.w) };
#pragma unroll
            for (int i = 0; i < 4; i++)
#pragma unroll
                for (int j = 0; j < 4; j++) ffma2(acc[i][j], A[i], Bv[j]);
        }
        __syncthreads();
    }

#pragma unroll
    for (int j = 0; j < 4; j++) {
        int n = n0 + tx * 4 + j;
        float bsv = bias[n];
#pragma unroll
        for (int i = 0; i < 4; i++) {
            float lo, hi;
            upk2(acc[i][j], lo, hi);
            int m_lo = m0 + ty * 8 + i * 2;
            int t0 = m_lo >> 5, b_lo = m_lo & 31;
            g_pre[(size_t)t0 * GG * BB + (size_t)n * BB + b_lo] = lo + bsv;
            int m_hi = m_lo + 1;
            int t1 = m_hi >> 5, b_hi = m_hi & 31;
            g_pre[(size_t)t1 * GG * BB + (size_t)n * BB + b_hi] = hi + bsv;
        }
    }
}

// =====================================================================
// Kernel B: persistent recurrent kernel, K-split register-tiled GEMM.
// CTA c owns cells [4c,4c+4) => 16 gate rows (r: q = r>>2, cell = r&3).
// Warp w owns k in [64w, 64w+64); lane = batch; 16 row-accumulators in
// registers, packed over k-parity (f32x2). h read from SMEM exactly once
// per step; weights stream as broadcast LDS.128 in FFMA2 operand layout.
// =====================================================================
struct __align__(16) SmemR {
    float  hT[BB][HPAD];       // transposed h, [b][k]                 ~66.3 KB
    float2 w2[8 * 32 * 16];    // [w][kp][r] = {w[r][k], w[r][k+1]}       32 KB
    float  gred[8][16][BB];    // per-warp partial gates                  16 KB
    float  cst[4][BB];         // cell state [cell][b]
    float  hsm[BB][4];         // h staging for coalesced writeback
};

__global__ __launch_bounds__(RTHREADS, 1) void lstm_recur(
    const float* __restrict__ h0, const float* __restrict__ c0,
    const float* __restrict__ w_hh, const float* __restrict__ b_hh,
    float* __restrict__ out, int write_state) {
    extern __shared__ char smem_raw[];
    SmemR* s = (SmemR*)smem_raw;

    const int tid = threadIdx.x;
    const int w = tid >> 5, lane = tid & 31;
    const int j0 = blockIdx.x * 4;

    // --- load packed k-pair weights into SMEM (once for all 2048 steps) ---
    // layout: w2[ww*512 + kp*16 + r], r = gate-row index (q = r>>2, cell = r&3)
    for (int idx = tid; idx < 8 * 32 * 16; idx += RTHREADS) {
        int ww = idx >> 9;
        int kp = (idx >> 4) & 31;
        int r  = idx & 15;
        int row = (r >> 2) * HH + j0 + (r & 3);
        int k = ww * 64 + kp * 2;
        s->w2[idx] = make_float2(w_hh[(size_t)row * HH + k],
                                 w_hh[(size_t)row * HH + k + 1]);
    }
    const int cc = (tid >> 5) & 3;   // cell (tid < 128 path)
    const int bb = tid & 31;         // batch
    float bh[4];
    if (tid < 128) {
        s->cst[cc][bb] = c0[(size_t)bb * HH + j0 + cc];
#pragma unroll
        for (int q = 0; q < 4; q++) bh[q] = b_hh[q * HH + j0 + cc];
    }
    __syncthreads();

    float h_keep = 0.f, c_keep = 0.f;

    for (int t = 0; t < TT; t++) {
        // ---- prefetch x-contribution for this step (hidden under staging) ----
        float pq[4];
        if (tid < 128) {
#pragma unroll
            for (int q = 0; q < 4; q++)
                pq[q] = __ldcg(&g_pre[(size_t)t * GG * BB +
                                      (size_t)(q * HH + j0 + cc) * BB + bb]);
        }

        // ---- stage h transposed into SMEM: hT[b][k] ----
        const float* hsrc = (t == 0) ? h0 : g_hbuf[t & 1];   // [b][k]
        for (int i = tid; i < (BB * HH) / 4; i += RTHREADS) {
            int b = i >> 7, kq = i & 127;
            float4 v = __ldcg((const float4*)(hsrc + (size_t)b * HH) + kq);
            float2* dst = (float2*)&s->hT[b][kq * 4];
            dst[0] = make_float2(v.x, v.y);
            dst[1] = make_float2(v.z, v.w);
        }
        __syncthreads();

        // ---- K-split gate GEMM: 16 rows x 32 batches, warp w does 64 k's ----
        unsigned long long acc[16];
#pragma unroll
        for (int r = 0; r < 16; r++) acc[r] = 0ull;
        {
            const unsigned long long* hrow =
                (const unsigned long long*)&s->hT[lane][w * 64];       // 32 k-pairs
            const ulonglong2* wv = (const ulonglong2*)&s->w2[w * 512]; // 8 u128 per kp
#pragma unroll 4
            for (int kp = 0; kp < 32; kp++) {
                unsigned long long H = hrow[kp];          // {h[k], h[k+1]}
                const ulonglong2* wq = wv + kp * 8;       // 16 float2 = 8 ulonglong2
#pragma unroll
                for (int i = 0; i < 8; i++) {
                    ulonglong2 q = wq[i];                 // rows 2i, 2i+1
                    ffma2(acc[2 * i + 0], H, q.x);
                    ffma2(acc[2 * i + 1], H, q.y);
                }
            }
        }

        // fold k-parity and publish per-warp partials
#pragma unroll
        for (int r = 0; r < 16; r++) {
            float lo, hi;
            upk2(acc[r], lo, hi);
            s->gred[w][r][lane] = lo + hi;
        }
        __syncthreads();

        // ---- reduce 8 warps + gates + cell update (128 threads) ----
        if (tid < 128) {
            float gate[4];
#pragma unroll
            for (int q = 0; q < 4; q++) {
                float ssum = pq[q] + bh[q];
#pragma unroll
                for (int ww = 0; ww < 8; ww++)
                    ssum += s->gred[ww][q * 4 + cc][bb];
                gate[q] = ssum;
            }
            float iv = sigmoid_f(gate[0]);
            float fv = sigmoid_f(gate[1]);
            float gv = tanh_f(gate[2]);
            float ov = sigmoid_f(gate[3]);
            float cn = fv * s->cst[cc][bb] + iv * gv;
            float hn = ov * tanh_f(cn);
            s->cst[cc][bb] = cn;
            s->hsm[bb][cc] = hn;
            h_keep = hn;
            c_keep = cn;
        }
        __syncthreads();

        // ---- coalesced writeback: next-h ping-pong + outputs[t] ----
        if (tid < 32) {
            float4 hv = *(const float4*)&s->hsm[tid][0];
            *(float4*)&g_hbuf[(t + 1) & 1][(size_t)tid * HH + j0] = hv;
            *(float4*)&out[(size_t)t * BB * HH + (size_t)tid * HH + j0] = hv;
        }
        __threadfence();

        // ---- grid barrier (sense-reversing; 2048 flips => ends at 0, replay-safe) ----
        {
            unsigned sense = (t & 1u) ^ 1u;
            __syncthreads();
            if (tid == 0) {
                unsigned arrived = atomicAdd(&g_count, 1u);
                if (arrived == NCTA - 1) {
                    atomicExch(&g_count, 0u);
                    __threadfence();
                    g_sense = sense;
                } else {
                    while (g_sense != sense) { __nanosleep(10); }
                    __threadfence();
                }
            }
            __syncthreads();
        }
    }

    if (write_state && tid < 128) {
        out[(size_t)TT * BB * HH + (size_t)bb * HH + j0 + cc] = h_keep;
        out[(size_t)TT * BB * HH + (size_t)BB * HH + (size_t)bb * HH + j0 + cc] = c_keep;
    }
}

// =====================================================================
// launch
// =====================================================================
extern "C" void kernel_launch(void* const* d_in, const int* in_sizes, int n_in,
                              void* d_out, int out_size) {
    const float* x    = (const float*)d_in[0];
    const float* h0   = (const float*)d_in[1];
    const float* c0   = (const float*)d_in[2];
    const float* w_ih = (const float*)d_in[3];
    const float* w_hh = (const float*)d_in[4];
    const float* b_ih = (const float*)d_in[5];
    const float* b_hh = (const float*)d_in[6];
    float* out = (float*)d_out;

    dim3 gridA(GG / BN, (TT * BB) / BM);
    pre_gemm<<<gridA, 256>>>(x, w_ih, b_ih);

    int smem = (int)sizeof(SmemR);
    cudaFuncSetAttribute(lstm_recur, cudaFuncAttributeMaxDynamicSharedMemorySize, smem);
    int write_state = (out_size >= TT * BB * HH + 2 * BB * HH) ? 1 : 0;
    lstm_recur<<<NCTA, RTHREADS, smem>>>(h0, c0, w_hh, b_hh, out, write_state);
}

// round 7
// speedup vs baseline: 1.7323x; 1.1768x over previous
#include <cuda_runtime.h>
#include <cstdint>
#include <math.h>

#define TT 2048
#define BB 32
#define DD 512
#define HH 512
#define GG 2048        // 4*H
#define NCTA 128       // persistent CTAs (one wave)
#define RTHREADS 256
#define HPAD 518       // hT row stride: even (8B loads), 259 mod 16 odd -> conflict-free LDS.64

// ---------------- device scratch (static, no allocs) ----------------
__device__ __align__(16) float g_pre[(size_t)TT * GG * BB];   // [t][gate_row][b]
__device__ __align__(16) float g_hbuf[2][BB * HH];            // ping-pong h, [b][k]
__device__ unsigned g_count;                                  // barrier counter (ends at 0)
__device__ unsigned g_sense;                                  // barrier sense (ends at 0)

// ---------------- packed fp32x2 helpers ----------------
__device__ __forceinline__ unsigned long long pk2(float lo, float hi) {
    unsigned long long r;
    asm("mov.b64 %0, {%1, %2};" : "=l"(r) : "f"(lo), "f"(hi));
    return r;
}
__device__ __forceinline__ void upk2(unsigned long long v, float& lo, float& hi) {
    asm("mov.b64 {%0, %1}, %2;" : "=f"(lo), "=f"(hi) : "l"(v));
}
__device__ __forceinline__ void ffma2(unsigned long long& acc, unsigned long long a,
                                      unsigned long long b) {
    asm("fma.rn.f32x2 %0, %1, %2, %0;" : "+l"(acc) : "l"(a), "l"(b));
}
__device__ __forceinline__ float sigmoid_f(float x) {
    return __fdividef(1.f, 1.f + __expf(-x));
}
__device__ __forceinline__ float tanh_f(float x) {
    return 2.f * __fdividef(1.f, 1.f + __expf(-2.f * x)) - 1.f;
}

// =====================================================================
// Kernel A: pre[t][g][b] = sum_k x[t][b][k] * w_ih[g][k] + b_ih[g]
// (unchanged; ~3.4ms, ~62% of packed-fp32 peak)
// =====================================================================
#define BM 128
#define BN 64
#define BK 16

__global__ __launch_bounds__(256) void pre_gemm(const float* __restrict__ x,
                                                const float* __restrict__ w,
                                                const float* __restrict__ bias) {
    __shared__ __align__(16) float As[BK][BM];
    __shared__ __align__(16) float Bs[BK][BN];

    const int m0 = blockIdx.y * BM;
    const int n0 = blockIdx.x * BN;
    const int tid = threadIdx.x;
    const int tx = tid & 15;
    const int ty = tid >> 4;

    unsigned long long acc[4][4];
#pragma unroll
    for (int i = 0; i < 4; i++)
#pragma unroll
        for (int j = 0; j < 4; j++) acc[i][j] = 0ull;

    for (int k0 = 0; k0 < DD; k0 += BK) {
#pragma unroll
        for (int l = 0; l < 2; l++) {
            int p = tid + l * 256;
            int row = p >> 2, kq = (p & 3) * 4;
            float4 v = *(const float4*)&x[(size_t)(m0 + row) * DD + k0 + kq];
            As[kq + 0][row] = v.x; As[kq + 1][row] = v.y;
            As[kq + 2][row] = v.z; As[kq + 3][row] = v.w;
        }
        {
            int row = tid >> 2, kq = (tid & 3) * 4;
            float4 v = *(const float4*)&w[(size_t)(n0 + row) * DD + k0 + kq];
            Bs[kq + 0][row] = v.x; Bs[kq + 1][row] = v.y;
            Bs[kq + 2][row] = v.z; Bs[kq + 3][row] = v.w;
        }
        __syncthreads();

#pragma unroll
        for (int k = 0; k < BK; k++) {
            float4 a01 = *(const float4*)&As[k][ty * 8];
            float4 a23 = *(const float4*)&As[k][ty * 8 + 4];
            float4 bf  = *(const float4*)&Bs[k][tx * 4];
            unsigned long long A[4] = { pk2(a01.x, a01.y), pk2(a01.z, a01.w),
                                        pk2(a23.x, a23.y), pk2(a23.z, a23.w) };
            unsigned long long Bv[4] = { pk2(bf.x, bf.x), pk2(bf.y, bf.y),
                                         pk2(bf.z, bf.z), pk2(bf.w, bf.w) };
#pragma unroll
            for (int i = 0; i < 4; i++)
#pragma unroll
                for (int j = 0; j < 4; j++) ffma2(acc[i][j], A[i], Bv[j]);
        }
        __syncthreads();
    }

#pragma unroll
    for (int j = 0; j < 4; j++) {
        int n = n0 + tx * 4 + j;
        float bsv = bias[n];
#pragma unroll
        for (int i = 0; i < 4; i++) {
            float lo, hi;
            upk2(acc[i][j], lo, hi);
            int m_lo = m0 + ty * 8 + i * 2;
            int t0 = m_lo >> 5, b_lo = m_lo & 31;
            g_pre[(size_t)t0 * GG * BB + (size_t)n * BB + b_lo] = lo + bsv;
            int m_hi = m_lo + 1;
            int t1 = m_hi >> 5, b_hi = m_hi & 31;
            g_pre[(size_t)t1 * GG * BB + (size_t)n * BB + b_hi] = hi + bsv;
        }
    }
}

// =====================================================================
// Kernel B: persistent recurrent kernel, latency-optimized.
//  - per-warp h staging (own k-slice only) + __syncwarp
//  - pipelined g_pre prefetch (t+1 loaded during step t)
//  - release/acquire grid barrier, no __threadfence, no membar.gl
// =====================================================================
struct __align__(16) SmemR {
    float  hT[BB][HPAD];       // transposed h, [b][k]                 ~66.3 KB
    float2 w2[8 * 32 * 16];    // [w][kp][r] = {w[r][k], w[r][k+1]}       32 KB
    float  gred[8][16][BB];    // per-warp partial gates                  16 KB
    float  cst[4][BB];         // cell state [cell][b]
    float  hsm[BB][4];         // h staging for coalesced writeback
};

__global__ __launch_bounds__(RTHREADS, 1) void lstm_recur(
    const float* __restrict__ h0, const float* __restrict__ c0,
    const float* __restrict__ w_hh, const float* __restrict__ b_hh,
    float* __restrict__ out, int write_state) {
    extern __shared__ char smem_raw[];
    SmemR* s = (SmemR*)smem_raw;

    const int tid = threadIdx.x;
    const int w = tid >> 5, lane = tid & 31;
    const int j0 = blockIdx.x * 4;

    // --- load packed k-pair weights into SMEM (once for all 2048 steps) ---
    for (int idx = tid; idx < 8 * 32 * 16; idx += RTHREADS) {
        int ww = idx >> 9;
        int kp = (idx >> 4) & 31;
        int r  = idx & 15;
        int row = (r >> 2) * HH + j0 + (r & 3);
        int k = ww * 64 + kp * 2;
        s->w2[idx] = make_float2(w_hh[(size_t)row * HH + k],
                                 w_hh[(size_t)row * HH + k + 1]);
    }
    const int cc = (tid >> 5) & 3;   // cell (tid<128 path)
    const int bb = tid & 31;         // batch
    float bh[4];
    float pq[4];                     // pipelined pre[t] values
    if (tid < 128) {
        s->cst[cc][bb] = c0[(size_t)bb * HH + j0 + cc];
#pragma unroll
        for (int q = 0; q < 4; q++) {
            bh[q] = b_hh[q * HH + j0 + cc];
            pq[q] = __ldcg(&g_pre[(size_t)(q * HH + j0 + cc) * BB + bb]);  // t=0
        }
    }
    __syncthreads();

    float h_keep = 0.f, c_keep = 0.f;

    for (int t = 0; t < TT; t++) {
        // ---- prefetch pre[t+1] into registers (used next step) ----
        float pqn[4];
        if (t + 1 < TT && tid < 128) {
#pragma unroll
            for (int q = 0; q < 4; q++)
                pqn[q] = __ldcg(&g_pre[(size_t)(t + 1) * GG * BB +
                                       (size_t)(q * HH + j0 + cc) * BB + bb]);
        }

        // ---- per-warp stage: warp w stages its own k-slice for all b ----
        const float* hsrc = (t == 0) ? h0 : g_hbuf[t & 1];   // [b][k]
#pragma unroll
        for (int it = 0; it < 16; it++) {
            int idx = it * 32 + lane;
            int b = idx >> 4, c = idx & 15;
            float4 v = __ldcg((const float4*)(hsrc + (size_t)b * HH + w * 64) + c);
            float2* dst = (float2*)&s->hT[b][w * 64 + c * 4];
            dst[0] = make_float2(v.x, v.y);
            dst[1] = make_float2(v.z, v.w);
        }
        __syncwarp();

        // ---- K-split gate GEMM: 16 rows x 32 batches, warp w does 64 k's ----
        unsigned long long acc[16];
#pragma unroll
        for (int r = 0; r < 16; r++) acc[r] = 0ull;
        {
            const unsigned long long* hrow =
                (const unsigned long long*)&s->hT[lane][w * 64];       // 32 k-pairs
            const ulonglong2* wv = (const ulonglong2*)&s->w2[w * 512];
#pragma unroll 4
            for (int kp = 0; kp < 32; kp++) {
                unsigned long long H = hrow[kp];
                const ulonglong2* wq = wv + kp * 8;       // 16 float2 = 8 ulonglong2
#pragma unroll
                for (int i = 0; i < 8; i++) {
                    ulonglong2 q = wq[i];                 // rows 2i, 2i+1
                    ffma2(acc[2 * i + 0], H, q.x);
                    ffma2(acc[2 * i + 1], H, q.y);
                }
            }
        }

        // fold k-parity and publish per-warp partials
#pragma unroll
        for (int r = 0; r < 16; r++) {
            float lo, hi;
            upk2(acc[r], lo, hi);
            s->gred[w][r][lane] = lo + hi;
        }
        __syncthreads();

        // ---- reduce 8 warps + gates + cell update (128 threads) ----
        if (tid < 128) {
            float gate[4];
#pragma unroll
            for (int q = 0; q < 4; q++) {
                float ssum = pq[q] + bh[q];
#pragma unroll
                for (int ww = 0; ww < 8; ww++)
                    ssum += s->gred[ww][q * 4 + cc][bb];
                gate[q] = ssum;
            }
            float iv = sigmoid_f(gate[0]);
            float fv = sigmoid_f(gate[1]);
            float gv = tanh_f(gate[2]);
            float ov = sigmoid_f(gate[3]);
            float cn = fv * s->cst[cc][bb] + iv * gv;
            float hn = ov * tanh_f(cn);
            s->cst[cc][bb] = cn;
            s->hsm[bb][cc] = hn;
            h_keep = hn;
            c_keep = cn;
#pragma unroll
            for (int q = 0; q < 4; q++) pq[q] = pqn[q];   // rotate pipeline
        }
        __syncthreads();

        // ---- writeback + release/acquire grid barrier ----
        if (tid < 32) {
            float4 hv = *(const float4*)&s->hsm[tid][0];
            *(float4*)&g_hbuf[(t + 1) & 1][(size_t)tid * HH + j0] = hv;
            *(float4*)&out[(size_t)t * BB * HH + (size_t)tid * HH + j0] = hv;
            __syncwarp();
            if (lane == 0) {
                unsigned sense = (t & 1u) ^ 1u;
                unsigned old;
                asm volatile("atom.add.release.gpu.u32 %0, [%1], %2;"
                             : "=r"(old) : "l"(&g_count), "r"(1u) : "memory");
                if (old == NCTA - 1) {
                    asm volatile("st.relaxed.gpu.u32 [%0], %1;"
                                 :: "l"(&g_count), "r"(0u) : "memory");
                    asm volatile("st.release.gpu.u32 [%0], %1;"
                                 :: "l"(&g_sense), "r"(sense) : "memory");
                } else {
                    unsigned v;
                    do {
                        asm volatile("ld.acquire.gpu.u32 %0, [%1];"
                                     : "=r"(v) : "l"(&g_sense) : "memory");
                    } while (v != sense);
                }
            }
        }
        __syncthreads();   // releases CTA once lane0 observed the new sense
    }

    if (write_state && tid < 128) {
        out[(size_t)TT * BB * HH + (size_t)bb * HH + j0 + cc] = h_keep;
        out[(size_t)TT * BB * HH + (size_t)BB * HH + (size_t)bb * HH + j0 + cc] = c_keep;
    }
}

// =====================================================================
// launch
// =====================================================================
extern "C" void kernel_launch(void* const* d_in, const int* in_sizes, int n_in,
                              void* d_out, int out_size) {
    const float* x    = (const float*)d_in[0];
    const float* h0   = (const float*)d_in[1];
    const float* c0   = (const float*)d_in[2];
    const float* w_ih = (const float*)d_in[3];
    const float* w_hh = (const float*)d_in[4];
    const float* b_ih = (const float*)d_in[5];
    const float* b_hh = (const float*)d_in[6];
    float* out = (float*)d_out;

    dim3 gridA(GG / BN, (TT * BB) / BM);
    pre_gemm<<<gridA, 256>>>(x, w_ih, b_ih);

    int smem = (int)sizeof(SmemR);
    cudaFuncSetAttribute(lstm_recur, cudaFuncAttributeMaxDynamicSharedMemorySize, smem);
    int write_state = (out_size >= TT * BB * HH + 2 * BB * HH) ? 1 : 0;
    lstm_recur<<<NCTA, RTHREADS, smem>>>(h0, c0, w_hh, b_hh, out, write_state);
}

// round 9
// speedup vs baseline: 1.7884x; 1.0324x over previous
#include <cuda_runtime.h>
#include <cstdint>
#include <math.h>

#define TT 2048
#define BB 32
#define DD 512
#define HH 512
#define GG 2048        // 4*H
#define NCTA 128       // persistent CTAs (one wave)
#define RTHREADS 512   // 16 warps
#define NW 16
#define KSL 32         // k-slice per warp
#define HPAD 518       // hT row stride: even (8B), pair-stride 259 odd -> 2-wf LDS.64 (minimum)

// ---------------- device scratch (static, no allocs) ----------------
__device__ __align__(16) float g_pre[(size_t)TT * GG * BB];   // [t][gate_row][b]
__device__ __align__(16) float g_hbuf[2][BB * HH];            // ping-pong h, [b][k]
__device__ __align__(128) unsigned g_flags[NCTA * 32];        // 1 flag per CTA, own 128B line

// ---------------- packed fp32x2 helpers ----------------
__device__ __forceinline__ unsigned long long pk2(float lo, float hi) {
    unsigned long long r;
    asm("mov.b64 %0, {%1, %2};" : "=l"(r) : "f"(lo), "f"(hi));
    return r;
}
__device__ __forceinline__ void upk2(unsigned long long v, float& lo, float& hi) {
    asm("mov.b64 {%0, %1}, %2;" : "=f"(lo), "=f"(hi) : "l"(v));
}
__device__ __forceinline__ void ffma2(unsigned long long& acc, unsigned long long a,
                                      unsigned long long b) {
    asm("fma.rn.f32x2 %0, %1, %2, %0;" : "+l"(acc) : "l"(a), "l"(b));
}
__device__ __forceinline__ float sigmoid_f(float x) {
    return __fdividef(1.f, 1.f + __expf(-x));
}
__device__ __forceinline__ float tanh_f(float x) {
    return 2.f * __fdividef(1.f, 1.f + __expf(-2.f * x)) - 1.f;
}

// =====================================================================
// Kernel A: pre[t][g][b] = sum_k x[t][b][k] * w_ih[g][k] + b_ih[g]
// (unchanged; ~3.3ms, ~57% of packed-fp32 peak)
// =====================================================================
#define BM 128
#define BN 64
#define BK 16

__global__ __launch_bounds__(256) void pre_gemm(const float* __restrict__ x,
                                                const float* __restrict__ w,
                                                const float* __restrict__ bias) {
    __shared__ __align__(16) float As[BK][BM];
    __shared__ __align__(16) float Bs[BK][BN];

    const int m0 = blockIdx.y * BM;
    const int n0 = blockIdx.x * BN;
    const int tid = threadIdx.x;
    const int tx = tid & 15;
    const int ty = tid >> 4;

    unsigned long long acc[4][4];
#pragma unroll
    for (int i = 0; i < 4; i++)
#pragma unroll
        for (int j = 0; j < 4; j++) acc[i][j] = 0ull;

    for (int k0 = 0; k0 < DD; k0 += BK) {
#pragma unroll
        for (int l = 0; l < 2; l++) {
            int p = tid + l * 256;
            int row = p >> 2, kq = (p & 3) * 4;
            float4 v = *(const float4*)&x[(size_t)(m0 + row) * DD + k0 + kq];
            As[kq + 0][row] = v.x; As[kq + 1][row] = v.y;
            As[kq + 2][row] = v.z; As[kq + 3][row] = v.w;
        }
        {
            int row = tid >> 2, kq = (tid & 3) * 4;
            float4 v = *(const float4*)&w[(size_t)(n0 + row) * DD + k0 + kq];
            Bs[kq + 0][row] = v.x; Bs[kq + 1][row] = v.y;
            Bs[kq + 2][row] = v.z; Bs[kq + 3][row] = v.w;
        }
        __syncthreads();

#pragma unroll
        for (int k = 0; k < BK; k++) {
            float4 a01 = *(const float4*)&As[k][ty * 8];
            float4 a23 = *(const float4*)&As[k][ty * 8 + 4];
            float4 bf  = *(const float4*)&Bs[k][tx * 4];
            unsigned long long A[4] = { pk2(a01.x, a01.y), pk2(a01.z, a01.w),
                                        pk2(a23.x, a23.y), pk2(a23.z, a23.w) };
            unsigned long long Bv[4] = { pk2(bf.x, bf.x), pk2(bf.y, bf.y),
                                         pk2(bf.z, bf.z), pk2(bf.w, bf.w) };
#pragma unroll
            for (int i = 0; i < 4; i++)
#pragma unroll
                for (int j = 0; j < 4; j++) ffma2(acc[i][j], A[i], Bv[j]);
        }
        __syncthreads();
    }

#pragma unroll
    for (int j = 0; j < 4; j++) {
        int n = n0 + tx * 4 + j;
        float bsv = bias[n];
#pragma unroll
        for (int i = 0; i < 4; i++) {
            float lo, hi;
            upk2(acc[i][j], lo, hi);
            int m_lo = m0 + ty * 8 + i * 2;
            int t0 = m_lo >> 5, b_lo = m_lo & 31;
            g_pre[(size_t)t0 * GG * BB + (size_t)n * BB + b_lo] = lo + bsv;
            int m_hi = m_lo + 1;
            int t1 = m_hi >> 5, b_hi = m_hi & 31;
            g_pre[(size_t)t1 * GG * BB + (size_t)n * BB + b_hi] = hi + bsv;
        }
    }
}

// =====================================================================
// Kernel B: persistent recurrent kernel, 16 warps, flag-array barrier.
// CTA c owns cells [4c,4c+4) => 16 gate rows. Warp w owns k in
// [32w, 32w+32); lane = batch; 16 row-accumulators packed over k-parity.
// =====================================================================
struct __align__(16) SmemR {
    float  hT[BB][HPAD];         // transposed h, [b][k]               ~66.3 KB
    float2 w2[NW * 16 * 16];     // [w][kp][r] = {w[r][k], w[r][k+1]}    32 KB
    float  gred[NW][16][BB];     // per-warp partial gates               32 KB
    float  cst[4][BB];           // cell state [cell][b]
    float  hsm[BB][4];           // h staging for coalesced writeback
};

__global__ __launch_bounds__(RTHREADS, 1) void lstm_recur(
    const float* __restrict__ h0, const float* __restrict__ c0,
    const float* __restrict__ w_hh, const float* __restrict__ b_hh,
    float* __restrict__ out, int write_state) {
    extern __shared__ char smem_raw[];
    SmemR* s = (SmemR*)smem_raw;

    const int tid = threadIdx.x;
    const int w = tid >> 5, lane = tid & 31;
    const int cid = blockIdx.x;
    const int j0 = cid * 4;

    // --- load packed k-pair weights into SMEM (once for all 2048 steps) ---
    // layout: w2[ww*256 + kp*16 + r]
    for (int idx = tid; idx < NW * 16 * 16; idx += RTHREADS) {
        int ww = idx >> 8;
        int kp = (idx >> 4) & 15;
        int r  = idx & 15;
        int row = (r >> 2) * HH + j0 + (r & 3);
        int k = ww * KSL + kp * 2;
        s->w2[idx] = make_float2(w_hh[(size_t)row * HH + k],
                                 w_hh[(size_t)row * HH + k + 1]);
    }
    const int cc = (tid >> 5) & 3;   // cell (tid<128 path)
    const int bb = tid & 31;         // batch
    float bh[4];
    float pq[4];                     // pipelined pre[t] values
    if (tid < 128) {
        s->cst[cc][bb] = c0[(size_t)bb * HH + j0 + cc];
#pragma unroll
        for (int q = 0; q < 4; q++) {
            bh[q] = b_hh[q * HH + j0 + cc];
            pq[q] = __ldcg(&g_pre[(size_t)(q * HH + j0 + cc) * BB + bb]);  // t=0
        }
    }
    __syncthreads();

    float h_keep = 0.f, c_keep = 0.f;

    for (int t = 0; t < TT; t++) {
        // ---- prefetch pre[t+1] into registers (used next step) ----
        float pqn[4];
        if (t + 1 < TT && tid < 128) {
#pragma unroll
            for (int q = 0; q < 4; q++)
                pqn[q] = __ldcg(&g_pre[(size_t)(t + 1) * GG * BB +
                                       (size_t)(q * HH + j0 + cc) * BB + bb]);
        }

        // ---- per-warp stage: warp w stages its 32-k slice for all b ----
        const float* hsrc = (t == 0) ? h0 : g_hbuf[t & 1];   // [b][k]
#pragma unroll
        for (int it = 0; it < 8; it++) {
            int idx = it * 32 + lane;
            int b = idx >> 3, c = idx & 7;
            float4 v = __ldcg((const float4*)(hsrc + (size_t)b * HH + w * KSL) + c);
            float2* dst = (float2*)&s->hT[b][w * KSL + c * 4];
            dst[0] = make_float2(v.x, v.y);
            dst[1] = make_float2(v.z, v.w);
        }
        __syncwarp();

        // ---- K-split gate GEMM: 16 rows x 32 batches, warp w does 32 k's ----
        unsigned long long acc[16];
#pragma unroll
        for (int r = 0; r < 16; r++) acc[r] = 0ull;
        {
            const unsigned long long* hrow =
                (const unsigned long long*)&s->hT[lane][w * KSL];      // 16 k-pairs
            const ulonglong2* wv = (const ulonglong2*)&s->w2[w * 256];
#pragma unroll 4
            for (int kp = 0; kp < 16; kp++) {
                unsigned long long H = hrow[kp];
                const ulonglong2* wq = wv + kp * 8;       // 16 float2 = 8 ulonglong2
#pragma unroll
                for (int i = 0; i < 8; i++) {
                    ulonglong2 q = wq[i];                 // rows 2i, 2i+1
                    ffma2(acc[2 * i + 0], H, q.x);
                    ffma2(acc[2 * i + 1], H, q.y);
                }
            }
        }

        // fold k-parity and publish per-warp partials
#pragma unroll
        for (int r = 0; r < 16; r++) {
            float lo, hi;
            upk2(acc[r], lo, hi);
            s->gred[w][r][lane] = lo + hi;
        }
        __syncthreads();

        // ---- reduce 16 warps + gates + cell update (128 threads) ----
        if (tid < 128) {
            float gate[4];
#pragma unroll
            for (int q = 0; q < 4; q++) {
                float ssum = pq[q] + bh[q];
#pragma unroll
                for (int ww = 0; ww < NW; ww++)
                    ssum += s->gred[ww][q * 4 + cc][bb];
                gate[q] = ssum;
            }
            float iv = sigmoid_f(gate[0]);
            float fv = sigmoid_f(gate[1]);
            float gv = tanh_f(gate[2]);
            float ov = sigmoid_f(gate[3]);
            float cn = fv * s->cst[cc][bb] + iv * gv;
            float hn = ov * tanh_f(cn);
            s->cst[cc][bb] = cn;
            s->hsm[bb][cc] = hn;
            h_keep = hn;
            c_keep = cn;
#pragma unroll
            for (int q = 0; q < 4; q++) pq[q] = pqn[q];   // rotate pipeline
        }
        __syncthreads();

        // ---- publish h + flag (release), then out[t] off critical path ----
        if (tid < 32) {
            float4 hv = *(const float4*)&s->hsm[tid][0];
            *(float4*)&g_hbuf[(t + 1) & 1][(size_t)tid * HH + j0] = hv;
            __syncwarp();
            if (lane == 0) {
                asm volatile("st.release.gpu.u32 [%0], %1;"
                             :: "l"(&g_flags[cid * 32]), "r"((unsigned)(t + 1))
                             : "memory");
            }
            // out[t] write does not gate the next step
            *(float4*)&out[(size_t)t * BB * HH + (size_t)tid * HH + j0] = hv;
        }

        // ---- flag-array wait: 128 lanes each poll one CTA's flag ----
        if (tid < NCTA) {
            unsigned want = (unsigned)(t + 1);
            unsigned v;
            do {
                asm volatile("ld.acquire.gpu.u32 %0, [%1];"
                             : "=r"(v) : "l"(&g_flags[tid * 32]) : "memory");
            } while (v - want > 1u);   // pass on v == t+1 or t+2 (owner <=1 ahead)
        }
        __syncthreads();
    }

    if (write_state && tid < 128) {
        out[(size_t)TT * BB * HH + (size_t)bb * HH + j0 + cc] = h_keep;
        out[(size_t)TT * BB * HH + (size_t)BB * HH + (size_t)bb * HH + j0 + cc] = c_keep;
    }
}

// =====================================================================
// launch
// =====================================================================
extern "C" void kernel_launch(void* const* d_in, const int* in_sizes, int n_in,
                              void* d_out, int out_size) {
    const float* x    = (const float*)d_in[0];
    const float* h0   = (const float*)d_in[1];
    const float* c0   = (const float*)d_in[2];
    const float* w_ih = (const float*)d_in[3];
    const float* w_hh = (const float*)d_in[4];
    const float* b_ih = (const float*)d_in[5];
    const float* b_hh = (const float*)d_in[6];
    float* out = (float*)d_out;

    dim3 gridA(GG / BN, (TT * BB) / BM);
    pre_gemm<<<gridA, 256>>>(x, w_ih, b_ih);

    int smem = (int)sizeof(SmemR);
    cudaFuncSetAttribute(lstm_recur, cudaFuncAttributeMaxDynamicSharedMemorySize, smem);
    int write_state = (out_size >= TT * BB * HH + 2 * BB * HH) ? 1 : 0;
    lstm_recur<<<NCTA, RTHREADS, smem>>>(h0, c0, w_hh, b_hh, out, write_state);
}